// round 9
// baseline (speedup 1.0000x reference)
#include <cuda_runtime.h>
#include <cuda_bf16.h>
#include <mma.h>
#include <cstdint>

using namespace nvcuda;

// Fixed shapes
#define B_      2
#define L_      512
#define D_      256
#define KH      (D_ / 2)                 // 128 per K-half
#define TILE    64
#define THREADS 512
#define NCTA    (8 * 8 * 2)              // 128 CTAs, all co-resident (1/SM)
#define SST     264                      // 256 + 8 pad bf16 (528B rows, 16B mult)
#define TILE_ELEMS (TILE * SST)
#define SMEM_BYTES (4 * TILE_ELEMS * 2)  // 135168 B
#define PST     68                       // partial-buffer stride (floats)

// out[b,i,j] = sum_d x[b,i,d]*w1[d]*x[b,j,d] + bias
// (lin_i - lin_j cancels under (P+P^T)/2 symmetrization; w2 dead.)
// split-bf16 3-product: a*x ≈ ahi*xhi + ahi*xlo + alo*xhi (rel ~2^-18)

// Split-bf16 scratch, row-major [B_*L_][D_]
__device__ __nv_bfloat16 gAhi[B_*L_*D_];
__device__ __nv_bfloat16 gAlo[B_*L_*D_];
__device__ __nv_bfloat16 gBhi[B_*L_*D_];
__device__ __nv_bfloat16 gBlo[B_*L_*D_];

// software grid barrier state (self-resetting; phase monotonic across replays)
__device__ unsigned g_count = 0;
__device__ unsigned g_phase = 0;

__device__ __forceinline__ uint32_t cvt2(float a, float b) {
    __nv_bfloat162 h = __floats2bfloat162_rn(a, b);
    return *reinterpret_cast<uint32_t*>(&h);
}
__device__ __forceinline__ void split4(const float* v, uint2& hi, uint2& lo) {
    uint32_t h01 = cvt2(v[0], v[1]);
    uint32_t h23 = cvt2(v[2], v[3]);
    float f0 = __uint_as_float(h01 << 16);
    float f1 = __uint_as_float(h01 & 0xFFFF0000u);
    float f2 = __uint_as_float(h23 << 16);
    float f3 = __uint_as_float(h23 & 0xFFFF0000u);
    hi.x = h01; hi.y = h23;
    lo.x = cvt2(v[0] - f0, v[1] - f1);
    lo.y = cvt2(v[2] - f2, v[3] - f3);
}
__device__ __forceinline__ uint32_t smem_u32(const void* p) {
    uint32_t a;
    asm("{ .reg .u64 t; cvta.to.shared.u64 t, %1; cvt.u32.u64 %0, t; }" : "=r"(a) : "l"(p));
    return a;
}
__device__ __forceinline__ void cp_async16(uint32_t dst, const void* src) {
    asm volatile("cp.async.cg.shared.global [%0], [%1], 16;" :: "r"(dst), "l"(src));
}

__global__ __launch_bounds__(THREADS, 1)
void fused_pairwise_kernel(const float* __restrict__ x,
                           const float* __restrict__ W,
                           const float* __restrict__ bias_p,
                           float* __restrict__ out) {
    extern __shared__ __align__(16) __nv_bfloat16 smem[];
    __nv_bfloat16* sAhi = smem;
    __nv_bfloat16* sAlo = smem + TILE_ELEMS;
    __nv_bfloat16* sBhi = smem + 2 * TILE_ELEMS;
    __nv_bfloat16* sBlo = smem + 3 * TILE_ELEMS;
    float* P0 = (float*)smem;                 // partial buffers reuse operand smem
    float* P1 = (float*)(smem + TILE_ELEMS);

    const int bz  = blockIdx.z;
    const int ti  = blockIdx.y;
    const int tj  = blockIdx.x;
    const int tid = threadIdx.x;
    const int warp = tid >> 5;
    const int cta = (bz * 8 + ti) * 8 + tj;   // 0..127

    // ================= phase 0: convert 8 rows/CTA once =================
    {
        int row8 = tid >> 6;                  // 0..7
        int c4   = tid & 63;                  // float4 col
        int gr   = cta * 8 + row8;            // global row 0..1023
        float4 xv = ((const float4*)x)[gr * 64 + c4];
        float4 wv = ((const float4*)W)[c4];   // W[:256] = w1
        float av[4] = {xv.x * wv.x, xv.y * wv.y, xv.z * wv.z, xv.w * wv.w};
        float bv[4] = {xv.x, xv.y, xv.z, xv.w};
        uint2 ahi, alo, bhi, blo;
        split4(av, ahi, alo);
        split4(bv, bhi, blo);
        int gidx = gr * 64 + c4;              // uint2 index ([row][256] bf16)
        ((uint2*)gAhi)[gidx] = ahi;
        ((uint2*)gAlo)[gidx] = alo;
        ((uint2*)gBhi)[gidx] = bhi;
        ((uint2*)gBlo)[gidx] = blo;
    }
    __syncthreads();

    // ================= software grid barrier =================
    if (tid == 0) {
        unsigned my = *(volatile unsigned*)&g_phase;
        __threadfence();                       // publish phase-0 stores
        unsigned old = atomicAdd(&g_count, 1);
        if (old == NCTA - 1) {
            g_count = 0;
            __threadfence();
            atomicAdd(&g_phase, 1);
        } else {
            while (*(volatile unsigned*)&g_phase == my) { }
        }
        __threadfence();                       // acquire others' stores
    }
    __syncthreads();

    // ================= phase 1: cp.async tiles into smem =================
    const uint32_t sbase = smem_u32(smem);
    const size_t offA = (size_t)(bz * L_ + ti * TILE) * D_;
    const size_t offB = (size_t)(bz * L_ + tj * TILE) * D_;
    const __nv_bfloat16* srcs[4] = {gAhi + offA, gAlo + offA, gBhi + offB, gBlo + offB};
    #pragma unroll
    for (int m = 0; m < 4; m++) {
        const uint4* src = (const uint4*)srcs[m];
        uint32_t dbase = sbase + (uint32_t)(m * TILE_ELEMS) * 2;
        #pragma unroll
        for (int i = 0; i < 4; i++) {
            int lin = i * THREADS + tid;       // 0..2047 (16B chunks)
            int row = lin >> 5;                // 0..63
            int c   = lin & 31;
            cp_async16(dbase + (uint32_t)(row * SST + c * 8) * 2, src + row * 32 + c);
        }
    }
    asm volatile("cp.async.commit_group;" ::: "memory");
    asm volatile("cp.async.wait_group 0;" ::: "memory");
    __syncthreads();

    // ---- MMA: warps 0-7, 2x2 spatial x 2 K-halves, 32x32 per warp ----
    wmma::fragment<wmma::accumulator, 16, 16, 16, float> acc[2][2];
    const int wr = (warp >> 1) & 1;
    const int wc = warp & 1;
    const int kh = warp >> 2;

    if (warp < 8) {
        #pragma unroll
        for (int r = 0; r < 2; r++)
            #pragma unroll
            for (int c = 0; c < 2; c++)
                wmma::fill_fragment(acc[r][c], 0.0f);

        const int kbase = kh * KH;
        const __nv_bfloat16* Ah = sAhi + (wr * 32) * SST + kbase;
        const __nv_bfloat16* Al = sAlo + (wr * 32) * SST + kbase;
        const __nv_bfloat16* Bh = sBhi + (wc * 32) * SST + kbase;
        const __nv_bfloat16* Bl = sBlo + (wc * 32) * SST + kbase;

        #pragma unroll
        for (int kk = 0; kk < KH; kk += 16) {
            wmma::fragment<wmma::matrix_a, 16, 16, 16, __nv_bfloat16, wmma::row_major> ah[2], al[2];
            wmma::fragment<wmma::matrix_b, 16, 16, 16, __nv_bfloat16, wmma::col_major> bh[2], bl[2];
            #pragma unroll
            for (int r = 0; r < 2; r++) {
                wmma::load_matrix_sync(ah[r], Ah + r * 16 * SST + kk, SST);
                wmma::load_matrix_sync(al[r], Al + r * 16 * SST + kk, SST);
            }
            #pragma unroll
            for (int c = 0; c < 2; c++) {
                wmma::load_matrix_sync(bh[c], Bh + c * 16 * SST + kk, SST);
                wmma::load_matrix_sync(bl[c], Bl + c * 16 * SST + kk, SST);
            }
            #pragma unroll
            for (int r = 0; r < 2; r++) {
                #pragma unroll
                for (int c = 0; c < 2; c++) {
                    wmma::mma_sync(acc[r][c], ah[r], bh[c], acc[r][c]);
                    wmma::mma_sync(acc[r][c], ah[r], bl[c], acc[r][c]);
                    wmma::mma_sync(acc[r][c], al[r], bh[c], acc[r][c]);
                }
            }
        }
    }
    __syncthreads();   // operand reads done; smem becomes partial buffers

    if (warp < 8) {
        float* P = kh ? P1 : P0;
        #pragma unroll
        for (int r = 0; r < 2; r++)
            #pragma unroll
            for (int c = 0; c < 2; c++)
                wmma::store_matrix_sync(P + (wr * 32 + r * 16) * PST + wc * 32 + c * 16,
                                        acc[r][c], PST, wmma::mem_row_major);
    }
    __syncthreads();

    // ---- reduce + bias + STG ----
    const float bias = bias_p[0];
    float* obase = out + (size_t)bz * L_ * L_ + (size_t)(ti * TILE) * L_ + tj * TILE;
    #pragma unroll
    for (int i = 0; i < 2; i++) {
        int lin = i * THREADS + tid;
        int row = lin >> 4;
        int c4  = lin & 15;
        float4 v0 = *(float4*)&P0[row * PST + c4 * 4];
        float4 v1 = *(float4*)&P1[row * PST + c4 * 4];
        float4 o;
        o.x = v0.x + v1.x + bias;
        o.y = v0.y + v1.y + bias;
        o.z = v0.z + v1.z + bias;
        o.w = v0.w + v1.w + bias;
        *(float4*)(obase + (size_t)row * L_ + c4 * 4) = o;
    }
}

// ---------------------------------------------------------------------------
// d_in[0] = inputs f32 (2,512,256), d_in[1] = W f32 (512,1), d_in[2] = b f32 (1,)
// d_out   = f32 (2,512,512,1)
// ---------------------------------------------------------------------------
extern "C" void kernel_launch(void* const* d_in, const int* in_sizes, int n_in,
                              void* d_out, int out_size) {
    const float* x    = (const float*)d_in[0];
    const float* W    = (const float*)d_in[1];
    const float* bptr = (const float*)d_in[2];
    float* out = (float*)d_out;

    static bool attr_set = false;
    if (!attr_set) {
        cudaFuncSetAttribute(fused_pairwise_kernel,
                             cudaFuncAttributeMaxDynamicSharedMemorySize, SMEM_BYTES);
        attr_set = true;
    }

    dim3 grid(L_ / TILE, L_ / TILE, B_);   // (8, 8, 2) = 128 CTAs, 1/SM, single wave
    fused_pairwise_kernel<<<grid, THREADS, SMEM_BYTES>>>(x, W, bptr, out);
}